// round 2
// baseline (speedup 1.0000x reference)
#include <cuda_runtime.h>

// HMM forward for CgpHmmCell (nCodons=2): 24 states, batch=2048, T=2000.
// Two sequences per thread via native Blackwell f32x2 packed math.

#define T_LEN 2000
#define BATCH 2048
typedef unsigned long long u64;

__device__ float g_coef[17];       // runtime softmax'd transition coefficients
__device__ float g_pi[24];         // softmax(init_kernel)
__device__ float g_Bst[64 * 20];   // emission table, [ctx 0..63][state 0..16, pad to 20]

// ---------------------------------------------------------------------------
// Setup kernel (unchanged from R1)
// ---------------------------------------------------------------------------
__global__ void setup_kernel(const float* __restrict__ w,
                             const float* __restrict__ ew,
                             const float* __restrict__ ik) {
    int tid = threadIdx.x;
    if (tid == 0) {
        float w12 = w[12];
        float d1 = 1.0f - w12 * w12;
        float d2 = 1.0f - w12 * w12 * w12;
        {
            float v0 = 1.0f - w[0], v1 = w[0];
            float m = fmaxf(v0, v1);
            float e0 = expf(v0 - m), e1 = expf(v1 - m);
            float s = e0 + e1;
            g_coef[0] = e0 / s; g_coef[1] = e1 / s;
        }
        {
            float v0 = w[1], v1 = w[3], v2 = d1, v3 = d2;
            float m = fmaxf(fmaxf(v0, v1), fmaxf(v2, v3));
            float e0 = expf(v0 - m), e1 = expf(v1 - m), e2 = expf(v2 - m), e3 = expf(v3 - m);
            float s = e0 + e1 + e2 + e3;
            g_coef[2] = e0 / s; g_coef[3] = e1 / s; g_coef[4] = e2 / s; g_coef[5] = e3 / s;
        }
        {
            float v0 = w[2], v1 = w[4], v2 = d1;
            float m = fmaxf(fmaxf(v0, v1), v2);
            float e0 = expf(v0 - m), e1 = expf(v1 - m), e2 = expf(v2 - m);
            float s = e0 + e1 + e2;
            g_coef[6] = e0 / s; g_coef[7] = e1 / s; g_coef[8] = e2 / s;
        }
        {
            float v0 = w[5], v1 = 1.0f - w[5];
            float m = fmaxf(v0, v1);
            float e0 = expf(v0 - m), e1 = expf(v1 - m);
            float s = e0 + e1;
            g_coef[9] = e0 / s; g_coef[10] = e1 / s;
        }
        {
            float v0 = w[6], v1 = 1.0f - w[9];
            float m = fmaxf(v0, v1);
            float e0 = expf(v0 - m), e1 = expf(v1 - m);
            float s = e0 + e1;
            g_coef[11] = e0 / s; g_coef[12] = e1 / s;
        }
        {
            float v0 = w[7], v1 = 1.0f - w[10];
            float m = fmaxf(v0, v1);
            float e0 = expf(v0 - m), e1 = expf(v1 - m);
            float s = e0 + e1;
            g_coef[13] = e0 / s; g_coef[14] = e1 / s;
        }
        {
            float v0 = w[8], v1 = 1.0f - w[11];
            float m = fmaxf(v0, v1);
            float e0 = expf(v0 - m), e1 = expf(v1 - m);
            float s = e0 + e1;
            g_coef[15] = e0 / s; g_coef[16] = e1 / s;
        }
        {
            float m = -1e30f;
            for (int i = 0; i < 24; i++) m = fmaxf(m, ik[i]);
            float e[24]; float s = 0.0f;
            for (int i = 0; i < 24; i++) { e[i] = expf(ik[i] - m); s += e[i]; }
            for (int i = 0; i < 24; i++) g_pi[i] = e[i] / s;
        }
    }
    for (int idx = tid; idx < 17 * 16; idx += blockDim.x) {
        int s = idx >> 4;
        int pq = idx & 15;
        const float* p = ew + s * 64 + pq * 4;
        float v0 = p[0], v1 = p[1], v2 = p[2], v3 = p[3];
        float m = fmaxf(fmaxf(v0, v1), fmaxf(v2, v3));
        float e0 = expf(v0 - m), e1 = expf(v1 - m), e2 = expf(v2 - m), e3 = expf(v3 - m);
        float ss = e0 + e1 + e2 + e3;
        int base = pq * 4;
        g_Bst[(base + 0) * 20 + s] = e0 / ss;
        g_Bst[(base + 1) * 20 + s] = e1 / ss;
        g_Bst[(base + 2) * 20 + s] = e2 / ss;
        g_Bst[(base + 3) * 20 + s] = e3 / ss;
    }
}

// ---------------------------------------------------------------------------
// f32x2 helpers (native Blackwell packed fp32)
// ---------------------------------------------------------------------------
__device__ __forceinline__ u64 pk2(float lo, float hi) {
    u64 r; asm("mov.b64 %0, {%1,%2};" : "=l"(r) : "f"(lo), "f"(hi)); return r;
}
__device__ __forceinline__ void upk2(float& lo, float& hi, u64 p) {
    asm("mov.b64 {%0,%1}, %2;" : "=f"(lo), "=f"(hi) : "l"(p));
}
__device__ __forceinline__ u64 fma2(u64 a, u64 b, u64 c) {
    u64 d; asm("fma.rn.f32x2 %0,%1,%2,%3;" : "=l"(d) : "l"(a), "l"(b), "l"(c)); return d;
}
__device__ __forceinline__ u64 mul2(u64 a, u64 b) {
    u64 d; asm("mul.rn.f32x2 %0,%1,%2;" : "=l"(d) : "l"(a), "l"(b)); return d;
}
__device__ __forceinline__ u64 add2(u64 a, u64 b) {
    u64 d; asm("add.rn.f32x2 %0,%1,%2;" : "=l"(d) : "l"(a), "l"(b)); return d;
}

struct K2 {
    u64 a00, a01, a34, a37, a310, a314, a164, a1614, a67, a610,
        a197, a910, a2210;
    u64 a617s, a1917s, a920s, a2220s;   // pre-multiplied by 1/6
    u64 HALF, SIXTH, TWF;               // 0.5, 1/6, 1/12
};

// One packed forward step with emission: two sequences, contexts cA / cB.
__device__ __forceinline__ void step_E(const u64 (&s)[24], u64 (&d)[24],
                                       const float* __restrict__ Bsh,
                                       int cA, int cB, const K2& k) {
    const float4* rA = reinterpret_cast<const float4*>(Bsh + cA * 20);
    const float4* rB = reinterpret_cast<const float4*>(Bsh + cB * 20);
    float4 a0 = rA[0], a1 = rA[1], a2 = rA[2], a3 = rA[3];
    float4 b0 = rB[0], b1 = rB[1], b2 = rB[2], b3 = rB[3];
    float ea16 = Bsh[cA * 20 + 16], eb16 = Bsh[cB * 20 + 16];

    u64 t0  = mul2(k.a00, s[0]);
    u64 t1  = mul2(k.a01, s[0]);
    u64 t4  = fma2(k.a34,  s[3], mul2(k.a164,  s[16]));
    u64 t7  = fma2(k.a37,  s[3], fma2(k.a67,  s[6], mul2(k.a197, s[19])));
    u64 t10 = fma2(k.a310, s[3], fma2(k.a610, s[6], fma2(k.a910, s[9], mul2(k.a2210, s[22]))));
    u64 t13 = fma2(k.HALF, s[13], s[12]);
    u64 t14 = fma2(k.a314, s[3], mul2(k.a1614, s[16]));

    d[17] = fma2(k.a617s, s[6],  mul2(k.a1917s, s[19]));   // 1/6 folded into coefs
    d[20] = fma2(k.a920s, s[9],  mul2(k.a2220s, s[22]));
    d[23] = fma2(k.TWF,   s[13], mul2(k.SIXTH,  s[23]));
    d[18] = mul2(k.SIXTH, s[17]);
    d[19] = mul2(k.SIXTH, s[18]);
    d[21] = mul2(k.SIXTH, s[20]);
    d[22] = mul2(k.SIXTH, s[21]);

    d[0]  = mul2(t0,    pk2(a0.x, b0.x));
    d[1]  = mul2(t1,    pk2(a0.y, b0.y));
    d[2]  = mul2(s[1],  pk2(a0.z, b0.z));
    d[3]  = mul2(s[2],  pk2(a0.w, b0.w));
    d[4]  = mul2(t4,    pk2(a1.x, b1.x));
    d[5]  = mul2(s[4],  pk2(a1.y, b1.y));
    d[6]  = mul2(s[5],  pk2(a1.z, b1.z));
    d[7]  = mul2(t7,    pk2(a1.w, b1.w));
    d[8]  = mul2(s[7],  pk2(a2.x, b2.x));
    d[9]  = mul2(s[8],  pk2(a2.y, b2.y));
    d[10] = mul2(t10,   pk2(a2.z, b2.z));
    d[11] = mul2(s[10], pk2(a2.w, b2.w));
    d[12] = mul2(s[11], pk2(a3.x, b3.x));
    d[13] = mul2(t13,   pk2(a3.y, b3.y));
    d[14] = mul2(t14,   pk2(a3.z, b3.z));
    d[15] = mul2(s[14], pk2(a3.w, b3.w));
    d[16] = mul2(s[15], pk2(ea16, eb16));
}

__device__ __forceinline__ u64 sum24_2(const u64 (&a)[24]) {
    u64 s01 = add2(add2(a[0], a[1]),   add2(a[2], a[3]));
    u64 s23 = add2(add2(a[4], a[5]),   add2(a[6], a[7]));
    u64 s45 = add2(add2(a[8], a[9]),   add2(a[10], a[11]));
    u64 s67 = add2(add2(a[12], a[13]), add2(a[14], a[15]));
    u64 s89 = add2(add2(a[16], a[17]), add2(a[18], a[19]));
    u64 sab = add2(add2(a[20], a[21]), add2(a[22], a[23]));
    return add2(add2(add2(s01, s23), add2(s45, s67)), add2(s89, sab));
}

__global__ __launch_bounds__(32, 1)
void forward_kernel(const int* __restrict__ seq, float* __restrict__ out) {
    __shared__ __align__(16) float Bsh[64 * 20];
    for (int i = threadIdx.x; i < 64 * 20; i += 32) Bsh[i] = g_Bst[i];
    __syncthreads();

    float c[17];
    #pragma unroll
    for (int i = 0; i < 17; i++) c[i] = g_coef[i];

    const float S6 = 0.166666666666666667f;
    K2 k;
    k.a00    = pk2(c[0], c[0]);   k.a01   = pk2(c[1], c[1]);
    k.a34    = pk2(c[2], c[2]);   k.a314  = pk2(c[3], c[3]);
    k.a37    = pk2(c[4], c[4]);   k.a310  = pk2(c[5], c[5]);
    k.a67    = pk2(c[6], c[6]);   k.a610  = pk2(c[8], c[8]);
    k.a920s  = pk2(c[9] * S6, c[9] * S6);
    k.a910   = pk2(c[10], c[10]);
    k.a164   = pk2(c[11], c[11]); k.a1614 = pk2(c[12], c[12]);
    k.a197   = pk2(c[13], c[13]);
    k.a617s  = pk2(c[7] * S6, c[7] * S6);
    k.a1917s = pk2(c[14] * S6, c[14] * S6);
    k.a2210  = pk2(c[15], c[15]);
    k.a2220s = pk2(c[16] * S6, c[16] * S6);
    k.HALF   = pk2(0.5f, 0.5f);
    k.SIXTH  = pk2(S6, S6);
    k.TWF    = pk2(0.5f * S6, 0.5f * S6);

    int g = blockIdx.x * 32 + threadIdx.x;          // 0..1023
    const int4* qA = reinterpret_cast<const int4*>(seq + g * T_LEN);
    const int4* qB = reinterpret_cast<const int4*>(seq + (g + 1024) * T_LEN);

    // --- scalar prologue (t=1, uniform E absorbed), identical to R1 ---
    float P[24], Q[24];
    #pragma unroll
    for (int i = 0; i < 24; i++) P[i] = g_pi[i];
    {
        float t0  = c[0] * P[0];
        float t1  = c[1] * P[0];
        float t4  = fmaf(c[2],  P[3], c[11] * P[16]);
        float t7  = fmaf(c[4],  P[3], fmaf(c[6], P[6], c[13] * P[19]));
        float t10 = fmaf(c[5],  P[3], fmaf(c[8], P[6], fmaf(c[10], P[9], c[15] * P[22])));
        float t13 = fmaf(0.5f, P[13], P[12]);
        float t14 = fmaf(c[3],  P[3], c[12] * P[16]);
        float t17 = fmaf(c[7],  P[6], c[14] * P[19]);
        float t20 = fmaf(c[9],  P[9], c[16] * P[22]);
        float t23 = fmaf(0.5f, P[13], P[23]);
        Q[0] = t0;    Q[1] = t1;    Q[2] = P[1];  Q[3] = P[2];
        Q[4] = t4;    Q[5] = P[4];  Q[6] = P[5];  Q[7] = t7;
        Q[8] = P[7];  Q[9] = P[8];  Q[10] = t10;  Q[11] = P[10];
        Q[12] = P[11]; Q[13] = t13; Q[14] = t14;  Q[15] = P[14];
        Q[16] = P[15];
        Q[17] = t17;  Q[18] = P[17]; Q[19] = P[18];
        Q[20] = t20;  Q[21] = P[20]; Q[22] = P[21]; Q[23] = t23;
    }

    u64 SA[24], SB[24];
    #pragma unroll
    for (int i = 0; i < 24; i++) SB[i] = pk2(Q[i], Q[i]);

    int4 vA = qA[0], vB = qB[0];
    int cA = ((((vA.x << 2) | vA.y) << 2) | vA.z) & 63;
    int cB = ((((vB.x << 2) | vB.y) << 2) | vB.z) & 63;
    step_E(SB, SA, Bsh, cA, cB, k);                  // t=2
    cA = ((cA << 2) | vA.w) & 63;
    cB = ((cB << 2) | vB.w) & 63;
    step_E(SA, SB, Bsh, cA, cB, k);                  // t=3

    float llA = -3.58351893845611f;                  // 2*ln(1/6)
    float llB = -3.58351893845611f;

    for (int j = 1; j < 500; ++j) {
        int4 uA = qA[j], uB = qB[j];
        cA = ((cA << 2) | uA.x) & 63; cB = ((cB << 2) | uB.x) & 63; step_E(SB, SA, Bsh, cA, cB, k);
        cA = ((cA << 2) | uA.y) & 63; cB = ((cB << 2) | uB.y) & 63; step_E(SA, SB, Bsh, cA, cB, k);
        cA = ((cA << 2) | uA.z) & 63; cB = ((cB << 2) | uB.z) & 63; step_E(SB, SA, Bsh, cA, cB, k);
        cA = ((cA << 2) | uA.w) & 63; cB = ((cB << 2) | uB.w) & 63; step_E(SA, SB, Bsh, cA, cB, k);
        if ((j & 3) == 3) {
            u64 S2 = sum24_2(SB);
            float sA, sB;
            upk2(sA, sB, S2);
            llA += logf(sA);
            llB += logf(sB);
            u64 inv = pk2(1.0f / sA, 1.0f / sB);
            #pragma unroll
            for (int i = 0; i < 24; i++) SB[i] = mul2(SB[i], inv);
        }
    }
    out[g] = llA;
    out[g + 1024] = llB;
}

// ---------------------------------------------------------------------------
// Launch
// ---------------------------------------------------------------------------
extern "C" void kernel_launch(void* const* d_in, const int* in_sizes, int n_in,
                              void* d_out, int out_size) {
    const float* transition_kernel = (const float*)d_in[0];
    const float* emission_kernel   = (const float*)d_in[1];
    const float* init_kernel       = (const float*)d_in[2];
    const int*   seq               = (const int*)d_in[3];
    float* out = (float*)d_out;

    setup_kernel<<<1, 256>>>(transition_kernel, emission_kernel, init_kernel);
    forward_kernel<<<BATCH / 64, 32>>>(seq, out);
}

// round 3
// speedup vs baseline: 2.2433x; 2.2433x over previous
#include <cuda_runtime.h>

// HMM forward for CgpHmmCell (nCodons=2): 24 states, batch=2048, T=2000.
// One thread per sequence, 64 warps. States 18/19/21/22 beta-rescaled so the
// "copy x 1/6" updates become register renames. Seq int4 + E rows prefetched.

#define T_LEN 2000
#define BATCH 2048

__device__ float g_coef[17];       // prescaled transition coefficients
__device__ float g_raw[6];         // raw coefs needed by the no-E prologue step
__device__ float g_pi[24];         // softmax(init_kernel)
__device__ float g_Bst[64 * 20];   // emission table, [ctx 0..63][state 0..16, pad 20]

// ---------------------------------------------------------------------------
// Setup kernel
// ---------------------------------------------------------------------------
__global__ void setup_kernel(const float* __restrict__ w,
                             const float* __restrict__ ew,
                             const float* __restrict__ ik) {
    int tid = threadIdx.x;
    if (tid == 0) {
        float w12 = w[12];
        float d1 = 1.0f - w12 * w12;
        float d2 = 1.0f - w12 * w12 * w12;
        float a00, a01, a34, a314, a37, a310, a67, a617, a610,
              a920, a910, a164, a1614, a197, a1917, a2210, a2220;
        {
            float v0 = 1.0f - w[0], v1 = w[0];
            float m = fmaxf(v0, v1);
            float e0 = expf(v0 - m), e1 = expf(v1 - m);
            float s = e0 + e1;
            a00 = e0 / s; a01 = e1 / s;
        }
        {
            float v0 = w[1], v1 = w[3], v2 = d1, v3 = d2;
            float m = fmaxf(fmaxf(v0, v1), fmaxf(v2, v3));
            float e0 = expf(v0 - m), e1 = expf(v1 - m), e2 = expf(v2 - m), e3 = expf(v3 - m);
            float s = e0 + e1 + e2 + e3;
            a34 = e0 / s; a314 = e1 / s; a37 = e2 / s; a310 = e3 / s;
        }
        {
            float v0 = w[2], v1 = w[4], v2 = d1;
            float m = fmaxf(fmaxf(v0, v1), v2);
            float e0 = expf(v0 - m), e1 = expf(v1 - m), e2 = expf(v2 - m);
            float s = e0 + e1 + e2;
            a67 = e0 / s; a617 = e1 / s; a610 = e2 / s;
        }
        {
            float v0 = w[5], v1 = 1.0f - w[5];
            float m = fmaxf(v0, v1);
            float e0 = expf(v0 - m), e1 = expf(v1 - m);
            float s = e0 + e1;
            a920 = e0 / s; a910 = e1 / s;
        }
        {
            float v0 = w[6], v1 = 1.0f - w[9];
            float m = fmaxf(v0, v1);
            float e0 = expf(v0 - m), e1 = expf(v1 - m);
            float s = e0 + e1;
            a164 = e0 / s; a1614 = e1 / s;
        }
        {
            float v0 = w[7], v1 = 1.0f - w[10];
            float m = fmaxf(v0, v1);
            float e0 = expf(v0 - m), e1 = expf(v1 - m);
            float s = e0 + e1;
            a197 = e0 / s; a1917 = e1 / s;
        }
        {
            float v0 = w[8], v1 = 1.0f - w[11];
            float m = fmaxf(v0, v1);
            float e0 = expf(v0 - m), e1 = expf(v1 - m);
            float s = e0 + e1;
            a2210 = e0 / s; a2220 = e1 / s;
        }
        const float S6 = 1.0f / 6.0f, S36 = 1.0f / 36.0f, S216 = 1.0f / 216.0f;
        g_coef[0]  = a00;        g_coef[1]  = a01;
        g_coef[2]  = a34;        g_coef[3]  = a314;
        g_coef[4]  = a37;        g_coef[5]  = a310;
        g_coef[6]  = a67;        g_coef[7]  = a617 * S6;
        g_coef[8]  = a610;       g_coef[9]  = a920 * S6;
        g_coef[10] = a910;       g_coef[11] = a164;
        g_coef[12] = a1614;      g_coef[13] = a197 * S36;
        g_coef[14] = a1917 * S216; g_coef[15] = a2210 * S36;
        g_coef[16] = a2220 * S216;
        g_raw[0] = a617; g_raw[1] = a920; g_raw[2] = a197;
        g_raw[3] = a1917; g_raw[4] = a2210; g_raw[5] = a2220;
        {
            float m = -1e30f;
            for (int i = 0; i < 24; i++) m = fmaxf(m, ik[i]);
            float e[24]; float s = 0.0f;
            for (int i = 0; i < 24; i++) { e[i] = expf(ik[i] - m); s += e[i]; }
            for (int i = 0; i < 24; i++) g_pi[i] = e[i] / s;
        }
    }
    for (int idx = tid; idx < 17 * 16; idx += blockDim.x) {
        int s = idx >> 4;
        int pq = idx & 15;
        const float* p = ew + s * 64 + pq * 4;
        float v0 = p[0], v1 = p[1], v2 = p[2], v3 = p[3];
        float m = fmaxf(fmaxf(v0, v1), fmaxf(v2, v3));
        float e0 = expf(v0 - m), e1 = expf(v1 - m), e2 = expf(v2 - m), e3 = expf(v3 - m);
        float ss = e0 + e1 + e2 + e3;
        int base = pq * 4;
        g_Bst[(base + 0) * 20 + s] = e0 / ss;
        g_Bst[(base + 1) * 20 + s] = e1 / ss;
        g_Bst[(base + 2) * 20 + s] = e2 / ss;
        g_Bst[(base + 3) * 20 + s] = e3 / ss;
    }
}

// ---------------------------------------------------------------------------
// Forward kernel
// ---------------------------------------------------------------------------
struct Coef {
    float a00, a01, a34, a314, a37, a310, a67, a617, a610,
          a920, a910, a164, a1614, a197, a1917, a2210, a2220;
};

struct ERow { float4 e0, e1, e2, e3; float e16; };

__device__ __forceinline__ ERow loadE(const float* __restrict__ Bsh, int ctx) {
    const float4* r = reinterpret_cast<const float4*>(Bsh + ctx * 20);
    ERow e;
    e.e0 = r[0]; e.e1 = r[1]; e.e2 = r[2]; e.e3 = r[3];
    e.e16 = Bsh[ctx * 20 + 16];
    return e;
}

// One beta-rescaled forward step with register-resident emission row.
__device__ __forceinline__ void stepE(const float (&s)[24], float (&d)[24],
                                      const ERow& e, const Coef& k) {
    float t0  = k.a00 * s[0];
    float t1  = k.a01 * s[0];
    float t4  = fmaf(k.a34,  s[3], k.a164 * s[16]);
    float t7  = fmaf(k.a37,  s[3], fmaf(k.a67,  s[6], k.a197 * s[19]));
    float t10 = fmaf(k.a310, s[3], fmaf(k.a610, s[6], fmaf(k.a910, s[9], k.a2210 * s[22])));
    float t13 = fmaf(0.5f, s[13], s[12]);
    float t14 = fmaf(k.a314, s[3], k.a1614 * s[16]);
    d[17] = fmaf(k.a617, s[6], k.a1917 * s[19]);                 // prescaled coefs
    d[20] = fmaf(k.a920, s[9], k.a2220 * s[22]);
    d[23] = fmaf(0.0833333333333333f, s[13], 0.166666666666667f * s[23]);
    d[18] = s[17]; d[19] = s[18]; d[21] = s[20]; d[22] = s[21];  // free renames
    d[0]  = t0    * e.e0.x;  d[1]  = t1    * e.e0.y;
    d[2]  = s[1]  * e.e0.z;  d[3]  = s[2]  * e.e0.w;
    d[4]  = t4    * e.e1.x;  d[5]  = s[4]  * e.e1.y;
    d[6]  = s[5]  * e.e1.z;  d[7]  = t7    * e.e1.w;
    d[8]  = s[7]  * e.e2.x;  d[9]  = s[8]  * e.e2.y;
    d[10] = t10   * e.e2.z;  d[11] = s[10] * e.e2.w;
    d[12] = s[11] * e.e3.x;  d[13] = t13   * e.e3.y;
    d[14] = t14   * e.e3.z;  d[15] = s[14] * e.e3.w;
    d[16] = s[15] * e.e16;
}

__device__ __forceinline__ float sum24(const float (&a)[24]) {
    float s01 = (a[0] + a[1])   + (a[2] + a[3]);
    float s23 = (a[4] + a[5])   + (a[6] + a[7]);
    float s45 = (a[8] + a[9])   + (a[10] + a[11]);
    float s67 = (a[12] + a[13]) + (a[14] + a[15]);
    float s89 = (a[16] + a[17]) + (a[18] + a[19]);
    float sab = (a[20] + a[21]) + (a[22] + a[23]);
    return ((s01 + s23) + (s45 + s67)) + (s89 + sab);
}

__global__ __launch_bounds__(32, 1)
void forward_kernel(const int* __restrict__ seq, float* __restrict__ out) {
    __shared__ __align__(16) float Bsh[64 * 20];
    for (int i = threadIdx.x; i < 64 * 20; i += 32) Bsh[i] = g_Bst[i];
    __syncthreads();

    Coef k;
    k.a00   = g_coef[0];  k.a01   = g_coef[1];
    k.a34   = g_coef[2];  k.a314  = g_coef[3];
    k.a37   = g_coef[4];  k.a310  = g_coef[5];
    k.a67   = g_coef[6];  k.a617  = g_coef[7];
    k.a610  = g_coef[8];  k.a920  = g_coef[9];
    k.a910  = g_coef[10]; k.a164  = g_coef[11];
    k.a1614 = g_coef[12]; k.a197  = g_coef[13];
    k.a1917 = g_coef[14]; k.a2210 = g_coef[15];
    k.a2220 = g_coef[16];
    float r617 = g_raw[0], r920 = g_raw[1], r197 = g_raw[2],
          r1917 = g_raw[3], r2210 = g_raw[4], r2220 = g_raw[5];

    int b = blockIdx.x * 32 + threadIdx.x;
    const int4* q4 = reinterpret_cast<const int4*>(seq + b * T_LEN);

    float A[24], B[24];
    float P[24];
    #pragma unroll
    for (int i = 0; i < 24; i++) P[i] = g_pi[i];

    // t=1: pure transition step (raw coefs), then convert to beta scale.
    {
        float t0  = k.a00 * P[0];
        float t1  = k.a01 * P[0];
        float t4  = fmaf(k.a34,  P[3], k.a164 * P[16]);
        float t7  = fmaf(k.a37,  P[3], fmaf(k.a67,  P[6], r197 * P[19]));
        float t10 = fmaf(k.a310, P[3], fmaf(k.a610, P[6], fmaf(k.a910, P[9], r2210 * P[22])));
        float t13 = fmaf(0.5f, P[13], P[12]);
        float t14 = fmaf(k.a314, P[3], k.a1614 * P[16]);
        float t17 = fmaf(r617, P[6], r1917 * P[19]);
        float t20 = fmaf(r920, P[9], r2220 * P[22]);
        float t23 = fmaf(0.5f, P[13], P[23]);
        B[0] = t0;    B[1] = t1;    B[2] = P[1];  B[3] = P[2];
        B[4] = t4;    B[5] = P[4];  B[6] = P[5];  B[7] = t7;
        B[8] = P[7];  B[9] = P[8];  B[10] = t10;  B[11] = P[10];
        B[12] = P[11]; B[13] = t13; B[14] = t14;  B[15] = P[14];
        B[16] = P[15];
        B[17] = t17;
        B[18] = 6.0f  * P[17];   // beta scale
        B[19] = 36.0f * P[18];
        B[20] = t20;
        B[21] = 6.0f  * P[20];
        B[22] = 36.0f * P[21];
        B[23] = t23;
    }

    int4 v = q4[0];
    {
        int c2 = ((((v.x << 2) | v.y) << 2) | v.z) & 63;
        int c3 = ((c2 << 2) | v.w) & 63;
        ERow e2 = loadE(Bsh, c2), e3 = loadE(Bsh, c3);
        stepE(B, A, e2, k);   // t=2
        stepE(A, B, e3, k);   // t=3
    }
    int ctx = ((((v.y << 2) | v.z) << 2) | v.w) & 63;

    float loglik = -3.58351893845611f;   // 2*ln(1/6)

    int4 u = q4[1];
    for (int j = 1; j < 500; ++j) {
        int jn = (j < 499) ? j + 1 : j;
        int4 un = q4[jn];                // prefetch next block
        int c0 = ((ctx << 2) | u.x) & 63;
        int c1 = ((c0  << 2) | u.y) & 63;
        int c2 = ((c1  << 2) | u.z) & 63;
        int c3 = ((c2  << 2) | u.w) & 63;
        ctx = c3;
        ERow e0 = loadE(Bsh, c0);
        ERow e1 = loadE(Bsh, c1);
        ERow e2 = loadE(Bsh, c2);
        ERow e3 = loadE(Bsh, c3);
        stepE(B, A, e0, k);
        stepE(A, B, e1, k);
        stepE(B, A, e2, k);
        stepE(A, B, e3, k);
        if ((j & 3) == 3) {
            float S = sum24(B);
            loglik += logf(S);
            float inv = 1.0f / S;
            #pragma unroll
            for (int i = 0; i < 24; i++) B[i] *= inv;
        }
        u = un;
    }

    // Final beta -> alpha mass correction: sum(beta_j / d_j).
    const float S6 = 1.0f / 6.0f, S36 = 1.0f / 36.0f;
    float Sf = (B[0] + B[1]) + (B[2] + B[3]) + (B[4] + B[5]) + (B[6] + B[7])
             + (B[8] + B[9]) + (B[10] + B[11]) + (B[12] + B[13]) + (B[14] + B[15])
             + (B[16] + B[17]) + (B[20] + B[23])
             + S6 * (B[18] + B[21]) + S36 * (B[19] + B[22]);
    loglik += logf(Sf);

    out[b] = loglik;
}

// ---------------------------------------------------------------------------
// Launch
// ---------------------------------------------------------------------------
extern "C" void kernel_launch(void* const* d_in, const int* in_sizes, int n_in,
                              void* d_out, int out_size) {
    const float* transition_kernel = (const float*)d_in[0];
    const float* emission_kernel   = (const float*)d_in[1];
    const float* init_kernel       = (const float*)d_in[2];
    const int*   seq               = (const int*)d_in[3];
    float* out = (float*)d_out;

    setup_kernel<<<1, 256>>>(transition_kernel, emission_kernel, init_kernel);
    forward_kernel<<<BATCH / 32, 32>>>(seq, out);
}

// round 4
// speedup vs baseline: 2.2711x; 1.0124x over previous
#include <cuda_runtime.h>

// HMM forward for CgpHmmCell (nCodons=2): 24 states, batch=2048, T=2000.
// One thread per sequence, 64 warps. States 18/19/21/22 beta-rescaled so the
// "copy x 1/6" updates become register renames. Seq int4 + E rows prefetched.

#define T_LEN 2000
#define BATCH 2048

__device__ float g_coef[17];       // prescaled transition coefficients
__device__ float g_raw[6];         // raw coefs needed by the no-E prologue step
__device__ float g_pi[24];         // softmax(init_kernel)
__device__ float g_Bst[64 * 20];   // emission table, [ctx 0..63][state 0..16, pad 20]

// ---------------------------------------------------------------------------
// Setup kernel
// ---------------------------------------------------------------------------
__global__ void setup_kernel(const float* __restrict__ w,
                             const float* __restrict__ ew,
                             const float* __restrict__ ik) {
    int tid = threadIdx.x;
    if (tid == 0) {
        float w12 = w[12];
        float d1 = 1.0f - w12 * w12;
        float d2 = 1.0f - w12 * w12 * w12;
        float a00, a01, a34, a314, a37, a310, a67, a617, a610,
              a920, a910, a164, a1614, a197, a1917, a2210, a2220;
        {
            float v0 = 1.0f - w[0], v1 = w[0];
            float m = fmaxf(v0, v1);
            float e0 = expf(v0 - m), e1 = expf(v1 - m);
            float s = e0 + e1;
            a00 = e0 / s; a01 = e1 / s;
        }
        {
            float v0 = w[1], v1 = w[3], v2 = d1, v3 = d2;
            float m = fmaxf(fmaxf(v0, v1), fmaxf(v2, v3));
            float e0 = expf(v0 - m), e1 = expf(v1 - m), e2 = expf(v2 - m), e3 = expf(v3 - m);
            float s = e0 + e1 + e2 + e3;
            a34 = e0 / s; a314 = e1 / s; a37 = e2 / s; a310 = e3 / s;
        }
        {
            float v0 = w[2], v1 = w[4], v2 = d1;
            float m = fmaxf(fmaxf(v0, v1), v2);
            float e0 = expf(v0 - m), e1 = expf(v1 - m), e2 = expf(v2 - m);
            float s = e0 + e1 + e2;
            a67 = e0 / s; a617 = e1 / s; a610 = e2 / s;
        }
        {
            float v0 = w[5], v1 = 1.0f - w[5];
            float m = fmaxf(v0, v1);
            float e0 = expf(v0 - m), e1 = expf(v1 - m);
            float s = e0 + e1;
            a920 = e0 / s; a910 = e1 / s;
        }
        {
            float v0 = w[6], v1 = 1.0f - w[9];
            float m = fmaxf(v0, v1);
            float e0 = expf(v0 - m), e1 = expf(v1 - m);
            float s = e0 + e1;
            a164 = e0 / s; a1614 = e1 / s;
        }
        {
            float v0 = w[7], v1 = 1.0f - w[10];
            float m = fmaxf(v0, v1);
            float e0 = expf(v0 - m), e1 = expf(v1 - m);
            float s = e0 + e1;
            a197 = e0 / s; a1917 = e1 / s;
        }
        {
            float v0 = w[8], v1 = 1.0f - w[11];
            float m = fmaxf(v0, v1);
            float e0 = expf(v0 - m), e1 = expf(v1 - m);
            float s = e0 + e1;
            a2210 = e0 / s; a2220 = e1 / s;
        }
        const float S6 = 1.0f / 6.0f, S36 = 1.0f / 36.0f, S216 = 1.0f / 216.0f;
        g_coef[0]  = a00;        g_coef[1]  = a01;
        g_coef[2]  = a34;        g_coef[3]  = a314;
        g_coef[4]  = a37;        g_coef[5]  = a310;
        g_coef[6]  = a67;        g_coef[7]  = a617 * S6;
        g_coef[8]  = a610;       g_coef[9]  = a920 * S6;
        g_coef[10] = a910;       g_coef[11] = a164;
        g_coef[12] = a1614;      g_coef[13] = a197 * S36;
        g_coef[14] = a1917 * S216; g_coef[15] = a2210 * S36;
        g_coef[16] = a2220 * S216;
        g_raw[0] = a617; g_raw[1] = a920; g_raw[2] = a197;
        g_raw[3] = a1917; g_raw[4] = a2210; g_raw[5] = a2220;
        {
            float m = -1e30f;
            for (int i = 0; i < 24; i++) m = fmaxf(m, ik[i]);
            float e[24]; float s = 0.0f;
            for (int i = 0; i < 24; i++) { e[i] = expf(ik[i] - m); s += e[i]; }
            for (int i = 0; i < 24; i++) g_pi[i] = e[i] / s;
        }
    }
    for (int idx = tid; idx < 17 * 16; idx += blockDim.x) {
        int s = idx >> 4;
        int pq = idx & 15;
        const float* p = ew + s * 64 + pq * 4;
        float v0 = p[0], v1 = p[1], v2 = p[2], v3 = p[3];
        float m = fmaxf(fmaxf(v0, v1), fmaxf(v2, v3));
        float e0 = expf(v0 - m), e1 = expf(v1 - m), e2 = expf(v2 - m), e3 = expf(v3 - m);
        float ss = e0 + e1 + e2 + e3;
        int base = pq * 4;
        g_Bst[(base + 0) * 20 + s] = e0 / ss;
        g_Bst[(base + 1) * 20 + s] = e1 / ss;
        g_Bst[(base + 2) * 20 + s] = e2 / ss;
        g_Bst[(base + 3) * 20 + s] = e3 / ss;
    }
}

// ---------------------------------------------------------------------------
// Forward kernel
// ---------------------------------------------------------------------------
struct Coef {
    float a00, a01, a34, a314, a37, a310, a67, a617, a610,
          a920, a910, a164, a1614, a197, a1917, a2210, a2220;
};

struct ERow { float4 e0, e1, e2, e3; float e16; };

__device__ __forceinline__ ERow loadE(const float* __restrict__ Bsh, int ctx) {
    const float4* r = reinterpret_cast<const float4*>(Bsh + ctx * 20);
    ERow e;
    e.e0 = r[0]; e.e1 = r[1]; e.e2 = r[2]; e.e3 = r[3];
    e.e16 = Bsh[ctx * 20 + 16];
    return e;
}

// One beta-rescaled forward step with register-resident emission row.
__device__ __forceinline__ void stepE(const float (&s)[24], float (&d)[24],
                                      const ERow& e, const Coef& k) {
    float t0  = k.a00 * s[0];
    float t1  = k.a01 * s[0];
    float t4  = fmaf(k.a34,  s[3], k.a164 * s[16]);
    float t7  = fmaf(k.a37,  s[3], fmaf(k.a67,  s[6], k.a197 * s[19]));
    float t10 = fmaf(k.a310, s[3], fmaf(k.a610, s[6], fmaf(k.a910, s[9], k.a2210 * s[22])));
    float t13 = fmaf(0.5f, s[13], s[12]);
    float t14 = fmaf(k.a314, s[3], k.a1614 * s[16]);
    d[17] = fmaf(k.a617, s[6], k.a1917 * s[19]);                 // prescaled coefs
    d[20] = fmaf(k.a920, s[9], k.a2220 * s[22]);
    d[23] = fmaf(0.0833333333333333f, s[13], 0.166666666666667f * s[23]);
    d[18] = s[17]; d[19] = s[18]; d[21] = s[20]; d[22] = s[21];  // free renames
    d[0]  = t0    * e.e0.x;  d[1]  = t1    * e.e0.y;
    d[2]  = s[1]  * e.e0.z;  d[3]  = s[2]  * e.e0.w;
    d[4]  = t4    * e.e1.x;  d[5]  = s[4]  * e.e1.y;
    d[6]  = s[5]  * e.e1.z;  d[7]  = t7    * e.e1.w;
    d[8]  = s[7]  * e.e2.x;  d[9]  = s[8]  * e.e2.y;
    d[10] = t10   * e.e2.z;  d[11] = s[10] * e.e2.w;
    d[12] = s[11] * e.e3.x;  d[13] = t13   * e.e3.y;
    d[14] = t14   * e.e3.z;  d[15] = s[14] * e.e3.w;
    d[16] = s[15] * e.e16;
}

__device__ __forceinline__ float sum24(const float (&a)[24]) {
    float s01 = (a[0] + a[1])   + (a[2] + a[3]);
    float s23 = (a[4] + a[5])   + (a[6] + a[7]);
    float s45 = (a[8] + a[9])   + (a[10] + a[11]);
    float s67 = (a[12] + a[13]) + (a[14] + a[15]);
    float s89 = (a[16] + a[17]) + (a[18] + a[19]);
    float sab = (a[20] + a[21]) + (a[22] + a[23]);
    return ((s01 + s23) + (s45 + s67)) + (s89 + sab);
}

__global__ __launch_bounds__(32, 1)
void forward_kernel(const int* __restrict__ seq, float* __restrict__ out) {
    __shared__ __align__(16) float Bsh[64 * 20];
    for (int i = threadIdx.x; i < 64 * 20; i += 32) Bsh[i] = g_Bst[i];
    __syncthreads();

    Coef k;
    k.a00   = g_coef[0];  k.a01   = g_coef[1];
    k.a34   = g_coef[2];  k.a314  = g_coef[3];
    k.a37   = g_coef[4];  k.a310  = g_coef[5];
    k.a67   = g_coef[6];  k.a617  = g_coef[7];
    k.a610  = g_coef[8];  k.a920  = g_coef[9];
    k.a910  = g_coef[10]; k.a164  = g_coef[11];
    k.a1614 = g_coef[12]; k.a197  = g_coef[13];
    k.a1917 = g_coef[14]; k.a2210 = g_coef[15];
    k.a2220 = g_coef[16];
    float r617 = g_raw[0], r920 = g_raw[1], r197 = g_raw[2],
          r1917 = g_raw[3], r2210 = g_raw[4], r2220 = g_raw[5];

    int b = blockIdx.x * 32 + threadIdx.x;
    const int4* q4 = reinterpret_cast<const int4*>(seq + b * T_LEN);

    float A[24], B[24];
    float P[24];
    #pragma unroll
    for (int i = 0; i < 24; i++) P[i] = g_pi[i];

    // t=1: pure transition step (raw coefs), then convert to beta scale.
    {
        float t0  = k.a00 * P[0];
        float t1  = k.a01 * P[0];
        float t4  = fmaf(k.a34,  P[3], k.a164 * P[16]);
        float t7  = fmaf(k.a37,  P[3], fmaf(k.a67,  P[6], r197 * P[19]));
        float t10 = fmaf(k.a310, P[3], fmaf(k.a610, P[6], fmaf(k.a910, P[9], r2210 * P[22])));
        float t13 = fmaf(0.5f, P[13], P[12]);
        float t14 = fmaf(k.a314, P[3], k.a1614 * P[16]);
        float t17 = fmaf(r617, P[6], r1917 * P[19]);
        float t20 = fmaf(r920, P[9], r2220 * P[22]);
        float t23 = fmaf(0.5f, P[13], P[23]);
        B[0] = t0;    B[1] = t1;    B[2] = P[1];  B[3] = P[2];
        B[4] = t4;    B[5] = P[4];  B[6] = P[5];  B[7] = t7;
        B[8] = P[7];  B[9] = P[8];  B[10] = t10;  B[11] = P[10];
        B[12] = P[11]; B[13] = t13; B[14] = t14;  B[15] = P[14];
        B[16] = P[15];
        B[17] = t17;
        B[18] = 6.0f  * P[17];   // beta scale
        B[19] = 36.0f * P[18];
        B[20] = t20;
        B[21] = 6.0f  * P[20];
        B[22] = 36.0f * P[21];
        B[23] = t23;
    }

    int4 v = q4[0];
    {
        int c2 = ((((v.x << 2) | v.y) << 2) | v.z) & 63;
        int c3 = ((c2 << 2) | v.w) & 63;
        ERow e2 = loadE(Bsh, c2), e3 = loadE(Bsh, c3);
        stepE(B, A, e2, k);   // t=2
        stepE(A, B, e3, k);   // t=3
    }
    int ctx = ((((v.y << 2) | v.z) << 2) | v.w) & 63;

    float loglik = -3.58351893845611f;   // 2*ln(1/6)

    int4 u = q4[1];
    for (int j = 1; j < 500; ++j) {
        int jn = (j < 499) ? j + 1 : j;
        int4 un = q4[jn];                // prefetch next block
        int c0 = ((ctx << 2) | u.x) & 63;
        int c1 = ((c0  << 2) | u.y) & 63;
        int c2 = ((c1  << 2) | u.z) & 63;
        int c3 = ((c2  << 2) | u.w) & 63;
        ctx = c3;
        ERow e0 = loadE(Bsh, c0);
        ERow e1 = loadE(Bsh, c1);
        ERow e2 = loadE(Bsh, c2);
        ERow e3 = loadE(Bsh, c3);
        stepE(B, A, e0, k);
        stepE(A, B, e1, k);
        stepE(B, A, e2, k);
        stepE(A, B, e3, k);
        if ((j & 3) == 3) {
            float S = sum24(B);
            loglik += logf(S);
            float inv = 1.0f / S;
            #pragma unroll
            for (int i = 0; i < 24; i++) B[i] *= inv;
        }
        u = un;
    }

    // Final beta -> alpha mass correction: sum(beta_j / d_j).
    const float S6 = 1.0f / 6.0f, S36 = 1.0f / 36.0f;
    float Sf = (B[0] + B[1]) + (B[2] + B[3]) + (B[4] + B[5]) + (B[6] + B[7])
             + (B[8] + B[9]) + (B[10] + B[11]) + (B[12] + B[13]) + (B[14] + B[15])
             + (B[16] + B[17]) + (B[20] + B[23])
             + S6 * (B[18] + B[21]) + S36 * (B[19] + B[22]);
    loglik += logf(Sf);

    out[b] = loglik;
}

// ---------------------------------------------------------------------------
// Launch
// ---------------------------------------------------------------------------
extern "C" void kernel_launch(void* const* d_in, const int* in_sizes, int n_in,
                              void* d_out, int out_size) {
    const float* transition_kernel = (const float*)d_in[0];
    const float* emission_kernel   = (const float*)d_in[1];
    const float* init_kernel       = (const float*)d_in[2];
    const int*   seq               = (const int*)d_in[3];
    float* out = (float*)d_out;

    setup_kernel<<<1, 256>>>(transition_kernel, emission_kernel, init_kernel);
    forward_kernel<<<BATCH / 32, 32>>>(seq, out);
}

// round 5
// speedup vs baseline: 2.5954x; 1.1428x over previous
#include <cuda_runtime.h>

// HMM forward for CgpHmmCell (nCodons=2): 24 states, batch=2048, T=2000.
// One thread per sequence, 64 warps. Beta-rescaled states; fast log/rcp;
// 8-step software-pipelined main loop, seq prefetch distance 2.

#define T_LEN 2000
#define BATCH 2048

__device__ float g_coef[17];
__device__ float g_raw[6];
__device__ float g_pi[24];
__device__ float g_Bst[64 * 20];

// ---------------------------------------------------------------------------
// Setup kernel (identical to R3)
// ---------------------------------------------------------------------------
__global__ void setup_kernel(const float* __restrict__ w,
                             const float* __restrict__ ew,
                             const float* __restrict__ ik) {
    int tid = threadIdx.x;
    if (tid == 0) {
        float w12 = w[12];
        float d1 = 1.0f - w12 * w12;
        float d2 = 1.0f - w12 * w12 * w12;
        float a00, a01, a34, a314, a37, a310, a67, a617, a610,
              a920, a910, a164, a1614, a197, a1917, a2210, a2220;
        {
            float v0 = 1.0f - w[0], v1 = w[0];
            float m = fmaxf(v0, v1);
            float e0 = expf(v0 - m), e1 = expf(v1 - m);
            float s = e0 + e1;
            a00 = e0 / s; a01 = e1 / s;
        }
        {
            float v0 = w[1], v1 = w[3], v2 = d1, v3 = d2;
            float m = fmaxf(fmaxf(v0, v1), fmaxf(v2, v3));
            float e0 = expf(v0 - m), e1 = expf(v1 - m), e2 = expf(v2 - m), e3 = expf(v3 - m);
            float s = e0 + e1 + e2 + e3;
            a34 = e0 / s; a314 = e1 / s; a37 = e2 / s; a310 = e3 / s;
        }
        {
            float v0 = w[2], v1 = w[4], v2 = d1;
            float m = fmaxf(fmaxf(v0, v1), v2);
            float e0 = expf(v0 - m), e1 = expf(v1 - m), e2 = expf(v2 - m);
            float s = e0 + e1 + e2;
            a67 = e0 / s; a617 = e1 / s; a610 = e2 / s;
        }
        {
            float v0 = w[5], v1 = 1.0f - w[5];
            float m = fmaxf(v0, v1);
            float e0 = expf(v0 - m), e1 = expf(v1 - m);
            float s = e0 + e1;
            a920 = e0 / s; a910 = e1 / s;
        }
        {
            float v0 = w[6], v1 = 1.0f - w[9];
            float m = fmaxf(v0, v1);
            float e0 = expf(v0 - m), e1 = expf(v1 - m);
            float s = e0 + e1;
            a164 = e0 / s; a1614 = e1 / s;
        }
        {
            float v0 = w[7], v1 = 1.0f - w[10];
            float m = fmaxf(v0, v1);
            float e0 = expf(v0 - m), e1 = expf(v1 - m);
            float s = e0 + e1;
            a197 = e0 / s; a1917 = e1 / s;
        }
        {
            float v0 = w[8], v1 = 1.0f - w[11];
            float m = fmaxf(v0, v1);
            float e0 = expf(v0 - m), e1 = expf(v1 - m);
            float s = e0 + e1;
            a2210 = e0 / s; a2220 = e1 / s;
        }
        const float S6 = 1.0f / 6.0f, S36 = 1.0f / 36.0f, S216 = 1.0f / 216.0f;
        g_coef[0]  = a00;          g_coef[1]  = a01;
        g_coef[2]  = a34;          g_coef[3]  = a314;
        g_coef[4]  = a37;          g_coef[5]  = a310;
        g_coef[6]  = a67;          g_coef[7]  = a617 * S6;
        g_coef[8]  = a610;         g_coef[9]  = a920 * S6;
        g_coef[10] = a910;         g_coef[11] = a164;
        g_coef[12] = a1614;        g_coef[13] = a197 * S36;
        g_coef[14] = a1917 * S216; g_coef[15] = a2210 * S36;
        g_coef[16] = a2220 * S216;
        g_raw[0] = a617; g_raw[1] = a920; g_raw[2] = a197;
        g_raw[3] = a1917; g_raw[4] = a2210; g_raw[5] = a2220;
        {
            float m = -1e30f;
            for (int i = 0; i < 24; i++) m = fmaxf(m, ik[i]);
            float e[24]; float s = 0.0f;
            for (int i = 0; i < 24; i++) { e[i] = expf(ik[i] - m); s += e[i]; }
            for (int i = 0; i < 24; i++) g_pi[i] = e[i] / s;
        }
    }
    for (int idx = tid; idx < 17 * 16; idx += blockDim.x) {
        int s = idx >> 4;
        int pq = idx & 15;
        const float* p = ew + s * 64 + pq * 4;
        float v0 = p[0], v1 = p[1], v2 = p[2], v3 = p[3];
        float m = fmaxf(fmaxf(v0, v1), fmaxf(v2, v3));
        float e0 = expf(v0 - m), e1 = expf(v1 - m), e2 = expf(v2 - m), e3 = expf(v3 - m);
        float ss = e0 + e1 + e2 + e3;
        int base = pq * 4;
        g_Bst[(base + 0) * 20 + s] = e0 / ss;
        g_Bst[(base + 1) * 20 + s] = e1 / ss;
        g_Bst[(base + 2) * 20 + s] = e2 / ss;
        g_Bst[(base + 3) * 20 + s] = e3 / ss;
    }
}

// ---------------------------------------------------------------------------
// Forward kernel
// ---------------------------------------------------------------------------
struct Coef {
    float a00, a01, a34, a314, a37, a310, a67, a617, a610,
          a920, a910, a164, a1614, a197, a1917, a2210, a2220;
};

struct ERow { float4 e0, e1, e2, e3; float e16; };

__device__ __forceinline__ ERow loadE(const float* __restrict__ Bsh, int ctx) {
    const float4* r = reinterpret_cast<const float4*>(Bsh + ctx * 20);
    ERow e;
    e.e0 = r[0]; e.e1 = r[1]; e.e2 = r[2]; e.e3 = r[3];
    e.e16 = Bsh[ctx * 20 + 16];
    return e;
}

__device__ __forceinline__ void stepE(const float (&s)[24], float (&d)[24],
                                      const ERow& e, const Coef& k) {
    float t0  = k.a00 * s[0];
    float t1  = k.a01 * s[0];
    float t4  = fmaf(k.a34,  s[3], k.a164 * s[16]);
    float t7  = fmaf(k.a37,  s[3], fmaf(k.a67,  s[6], k.a197 * s[19]));
    float t10 = fmaf(k.a310, s[3], fmaf(k.a610, s[6], fmaf(k.a910, s[9], k.a2210 * s[22])));
    float t13 = fmaf(0.5f, s[13], s[12]);
    float t14 = fmaf(k.a314, s[3], k.a1614 * s[16]);
    d[17] = fmaf(k.a617, s[6], k.a1917 * s[19]);
    d[20] = fmaf(k.a920, s[9], k.a2220 * s[22]);
    d[23] = fmaf(0.0833333333333333f, s[13], 0.166666666666667f * s[23]);
    d[18] = s[17]; d[19] = s[18]; d[21] = s[20]; d[22] = s[21];
    d[0]  = t0    * e.e0.x;  d[1]  = t1    * e.e0.y;
    d[2]  = s[1]  * e.e0.z;  d[3]  = s[2]  * e.e0.w;
    d[4]  = t4    * e.e1.x;  d[5]  = s[4]  * e.e1.y;
    d[6]  = s[5]  * e.e1.z;  d[7]  = t7    * e.e1.w;
    d[8]  = s[7]  * e.e2.x;  d[9]  = s[8]  * e.e2.y;
    d[10] = t10   * e.e2.z;  d[11] = s[10] * e.e2.w;
    d[12] = s[11] * e.e3.x;  d[13] = t13   * e.e3.y;
    d[14] = t14   * e.e3.z;  d[15] = s[14] * e.e3.w;
    d[16] = s[15] * e.e16;
}

__device__ __forceinline__ float sum24(const float (&a)[24]) {
    float s01 = (a[0] + a[1])   + (a[2] + a[3]);
    float s23 = (a[4] + a[5])   + (a[6] + a[7]);
    float s45 = (a[8] + a[9])   + (a[10] + a[11]);
    float s67 = (a[12] + a[13]) + (a[14] + a[15]);
    float s89 = (a[16] + a[17]) + (a[18] + a[19]);
    float sab = (a[20] + a[21]) + (a[22] + a[23]);
    return ((s01 + s23) + (s45 + s67)) + (s89 + sab);
}

__global__ __launch_bounds__(32, 1)
void forward_kernel(const int* __restrict__ seq, float* __restrict__ out) {
    __shared__ __align__(16) float Bsh[64 * 20];
    for (int i = threadIdx.x; i < 64 * 20; i += 32) Bsh[i] = g_Bst[i];
    __syncthreads();

    Coef k;
    k.a00   = g_coef[0];  k.a01   = g_coef[1];
    k.a34   = g_coef[2];  k.a314  = g_coef[3];
    k.a37   = g_coef[4];  k.a310  = g_coef[5];
    k.a67   = g_coef[6];  k.a617  = g_coef[7];
    k.a610  = g_coef[8];  k.a920  = g_coef[9];
    k.a910  = g_coef[10]; k.a164  = g_coef[11];
    k.a1614 = g_coef[12]; k.a197  = g_coef[13];
    k.a1917 = g_coef[14]; k.a2210 = g_coef[15];
    k.a2220 = g_coef[16];
    float r617 = g_raw[0], r920 = g_raw[1], r197 = g_raw[2],
          r1917 = g_raw[3], r2210 = g_raw[4], r2220 = g_raw[5];

    int b = blockIdx.x * 32 + threadIdx.x;
    const int4* q4 = reinterpret_cast<const int4*>(seq + b * T_LEN);

    float A[24], B[24];
    float P[24];
    #pragma unroll
    for (int i = 0; i < 24; i++) P[i] = g_pi[i];

    // t=1: pure transition step (raw coefs), then convert to beta scale.
    {
        float t0  = k.a00 * P[0];
        float t1  = k.a01 * P[0];
        float t4  = fmaf(k.a34,  P[3], k.a164 * P[16]);
        float t7  = fmaf(k.a37,  P[3], fmaf(k.a67,  P[6], r197 * P[19]));
        float t10 = fmaf(k.a310, P[3], fmaf(k.a610, P[6], fmaf(k.a910, P[9], r2210 * P[22])));
        float t13 = fmaf(0.5f, P[13], P[12]);
        float t14 = fmaf(k.a314, P[3], k.a1614 * P[16]);
        float t17 = fmaf(r617, P[6], r1917 * P[19]);
        float t20 = fmaf(r920, P[9], r2220 * P[22]);
        float t23 = fmaf(0.5f, P[13], P[23]);
        B[0] = t0;    B[1] = t1;    B[2] = P[1];  B[3] = P[2];
        B[4] = t4;    B[5] = P[4];  B[6] = P[5];  B[7] = t7;
        B[8] = P[7];  B[9] = P[8];  B[10] = t10;  B[11] = P[10];
        B[12] = P[11]; B[13] = t13; B[14] = t14;  B[15] = P[14];
        B[16] = P[15];
        B[17] = t17;
        B[18] = 6.0f  * P[17];
        B[19] = 36.0f * P[18];
        B[20] = t20;
        B[21] = 6.0f  * P[20];
        B[22] = 36.0f * P[21];
        B[23] = t23;
    }

    int4 v = q4[0];
    {
        int c2 = ((((v.x << 2) | v.y) << 2) | v.z) & 63;
        int c3 = ((c2 << 2) | v.w) & 63;
        ERow e2 = loadE(Bsh, c2), e3 = loadE(Bsh, c3);
        stepE(B, A, e2, k);   // t=2
        stepE(A, B, e3, k);   // t=3
    }
    int ctx = ((((v.y << 2) | v.z) << 2) | v.w) & 63;

    float loglik = -3.58351893845611f;   // 2*ln(1/6)

    // Software pipeline: seq int4 prefetch distance 2.
    int4 u0 = q4[1];
    int4 u1 = q4[2];
    #pragma unroll 2
    for (int j = 1; j < 500; ++j) {
        int jn = (j < 498) ? j + 2 : 499;
        int4 up = q4[jn];                 // prefetch (distance 2)
        int c0 = ((ctx << 2) | u0.x) & 63;
        int c1 = ((c0  << 2) | u0.y) & 63;
        int c2 = ((c1  << 2) | u0.z) & 63;
        int c3 = ((c2  << 2) | u0.w) & 63;
        ctx = c3;
        ERow e0 = loadE(Bsh, c0);
        ERow e1 = loadE(Bsh, c1);
        ERow e2 = loadE(Bsh, c2);
        ERow e3 = loadE(Bsh, c3);
        stepE(B, A, e0, k);
        stepE(A, B, e1, k);
        stepE(B, A, e2, k);
        stepE(A, B, e3, k);
        if ((j & 3) == 3) {
            float S = sum24(B);
            loglik += __logf(S);                  // fast MUFU log
            float inv = __fdividef(1.0f, S);      // fast rcp; error self-corrects
            #pragma unroll
            for (int i = 0; i < 24; i++) B[i] *= inv;
        }
        u0 = u1; u1 = up;
    }

    // Final beta -> alpha mass correction: sum(beta_j / d_j).
    const float S6 = 1.0f / 6.0f, S36 = 1.0f / 36.0f;
    float Sf = (B[0] + B[1]) + (B[2] + B[3]) + (B[4] + B[5]) + (B[6] + B[7])
             + (B[8] + B[9]) + (B[10] + B[11]) + (B[12] + B[13]) + (B[14] + B[15])
             + (B[16] + B[17]) + (B[20] + B[23])
             + S6 * (B[18] + B[21]) + S36 * (B[19] + B[22]);
    loglik += __logf(Sf);

    out[b] = loglik;
}

// ---------------------------------------------------------------------------
// Launch
// ---------------------------------------------------------------------------
extern "C" void kernel_launch(void* const* d_in, const int* in_sizes, int n_in,
                              void* d_out, int out_size) {
    const float* transition_kernel = (const float*)d_in[0];
    const float* emission_kernel   = (const float*)d_in[1];
    const float* init_kernel       = (const float*)d_in[2];
    const int*   seq               = (const int*)d_in[3];
    float* out = (float*)d_out;

    setup_kernel<<<1, 256>>>(transition_kernel, emission_kernel, init_kernel);
    forward_kernel<<<BATCH / 32, 32>>>(seq, out);
}